// round 7
// baseline (speedup 1.0000x reference)
#include <cuda_runtime.h>
#include <cuda_bf16.h>

// MaxBlurPooling1D: x (16, 8192, 256) f32 -> z (16, 4096, 256) f32
// z[b,j,c] = w0*m[2j-1] + w1*m[2j] + w2*m[2j+1] + w3*m[2j+2]
//   m[l] = max(x[l], x[l+1]) for l<=L-2 ; m[L-1] = x[L-1] ; m[-1] = m[L] = 0
//
// Round-6 changes vs round 4 (best = 30.5us kernel, DRAM 73.7%):
//  - PEEL the boundary iteration: for t in [0, JPT-2], r2 = 2(j0+t)+2 <= 8190
//    is ALWAYS in-bounds (j0 <= 4080), so the hot loop carries no guard at
//    all -> straight-line SASS, ptxas can front-batch loads across
//    iterations (bigger MLG window). Only the final iteration (1 check,
//    uniform) handles j = 4095.

#define L_DIM  8192
#define C4     64      // 256 f32 channels = 64 float4 lanes
#define J_OUT  4096
#define JPT    16      // outputs per thread along L
#define BY     2       // thread.y chunks per block

__device__ __forceinline__ float4 f4max(float4 a, float4 b) {
    return make_float4(fmaxf(a.x, b.x), fmaxf(a.y, b.y),
                       fmaxf(a.z, b.z), fmaxf(a.w, b.w));
}

__global__ void __launch_bounds__(128)
mbp1d_kernel(const float4* __restrict__ x,
             const float*  __restrict__ blur,
             const float*  __restrict__ avg,
             float4* __restrict__ z)
{
    // Fold blur (b0,b1,b2) and avg (a0,a1) into 4 taps over m[]
    const float b0 = blur[0], b1 = blur[1], b2 = blur[2];
    const float a0 = avg[0],  a1 = avg[1];
    const float w0 = a0 * b0;
    const float w1 = a0 * b1 + a1 * b0;
    const float w2 = a0 * b2 + a1 * b1;
    const float w3 = a1 * b2;

    const int c  = threadIdx.x;                                   // 0..63 float4 lane
    const int b  = blockIdx.y;                                    // batch
    const int j0 = (blockIdx.x * BY + threadIdx.y) * JPT;         // first output row

    const float4* xb = x + (size_t)b * L_DIM * C4 + c;
    float4*       zb = z + ((size_t)b * J_OUT + j0) * C4 + c;

    const float4 zero = make_float4(0.f, 0.f, 0.f, 0.f);

    // Rolling state at loop top for iteration j:
    //   mA = m[2j-1], mB = m[2j], xlast = x[2j+1]
    float4 mA, mB, xlast;
    {
        const float4 x0 = xb[(size_t)(2 * j0) * C4];
        const float4 x1 = xb[(size_t)(2 * j0 + 1) * C4];
        if (j0 == 0) {
            mA = zero;                                            // m[-1] = 0 (pad)
        } else {
            const float4 xm1 = xb[(size_t)(2 * j0 - 1) * C4];
            mA = f4max(xm1, x0);
        }
        mB = f4max(x0, x1);
        xlast = x1;
    }

    // Hot loop: t in [0, JPT-2]. r2 = 2(j0+t)+2 <= 2*4094+2 = 8190 < L_DIM,
    // so NO bounds check needed -> branch-free straight-line body.
    #pragma unroll
    for (int t = 0; t < JPT - 1; ++t) {
        const size_t r2 = (size_t)(2 * (j0 + t) + 2);
        const float4 x2 = xb[r2 * C4];
        const float4 x3 = xb[(r2 + 1) * C4];
        const float4 mC = f4max(xlast, x2);                       // m[2j+1]
        const float4 mD = f4max(x2, x3);                          // m[2j+2]
        xlast = x3;

        float4 o;
        o.x = w0 * mA.x + w1 * mB.x + w2 * mC.x + w3 * mD.x;
        o.y = w0 * mA.y + w1 * mB.y + w2 * mC.y + w3 * mD.y;
        o.z = w0 * mA.z + w1 * mB.z + w2 * mC.z + w3 * mD.z;
        o.w = w0 * mA.w + w1 * mB.w + w2 * mC.w + w3 * mD.w;
        zb[(size_t)t * C4] = o;

        mA = mC;
        mB = mD;
    }

    // Peeled final iteration: t = JPT-1, j = j0+15. Only j = 4095 (the very
    // last chunk) runs out of rows; uniform branch, taken by 1/64 of blocks.
    {
        const int t  = JPT - 1;
        const int j  = j0 + t;
        const int r2 = 2 * j + 2;
        float4 mC, mD;
        if (r2 < L_DIM) {
            const float4 x2 = xb[(size_t)r2 * C4];
            const float4 x3 = xb[(size_t)(r2 + 1) * C4];
            mC = f4max(xlast, x2);
            mD = f4max(x2, x3);
        } else {
            // j = 4095: m[8191] = x[8191] (pad is NEG_INF), m[8192] = 0
            mC = xlast;
            mD = zero;
        }

        float4 o;
        o.x = w0 * mA.x + w1 * mB.x + w2 * mC.x + w3 * mD.x;
        o.y = w0 * mA.y + w1 * mB.y + w2 * mC.y + w3 * mD.y;
        o.z = w0 * mA.z + w1 * mB.z + w2 * mC.z + w3 * mD.z;
        o.w = w0 * mA.w + w1 * mB.w + w2 * mC.w + w3 * mD.w;
        zb[(size_t)t * C4] = o;
    }
}

extern "C" void kernel_launch(void* const* d_in, const int* in_sizes, int n_in,
                              void* d_out, int out_size)
{
    const float4* x    = (const float4*)d_in[0];   // (16, 8192, 256) f32
    const float*  blur = (const float*)d_in[1];    // (3,1,1)
    const float*  avg  = (const float*)d_in[2];    // (2,1,1)
    float4*       z    = (float4*)d_out;           // (16, 4096, 256) f32

    (void)in_sizes; (void)n_in; (void)out_size;

    dim3 block(C4, BY);                            // (64, 2) = 128 threads
    dim3 grid(J_OUT / (BY * JPT), 16);             // (128, 16) = 2048 blocks
    mbp1d_kernel<<<grid, block>>>(x, blur, avg, z);
}

// round 8
// speedup vs baseline: 1.0704x; 1.0704x over previous
#include <cuda_runtime.h>
#include <cuda_bf16.h>

// MaxBlurPooling1D: x (16, 8192, 256) f32 -> z (16, 4096, 256) f32
// z[b,j,c] = w0*m[2j-1] + w1*m[2j] + w2*m[2j+1] + w3*m[2j+2]
//   m[l] = max(x[l], x[l+1]) for l<=L-2 ; m[L-1] = x[L-1] ; m[-1] = m[L] = 0
//
// Round-7: force MLP structurally. Evidence from R1..R6: builds where ptxas
// front-batches loads (regs~54) hit 73% DRAM; builds where it interleaves
// (regs~40) hit 61-64%. So make batching mandatory: each group loads its 8
// input rows into independent registers BEFORE any max/fma consumes them.
// 4 groups x (8 loads -> 8 maxes -> 4 outputs). Groups 0-2 provably
// in-bounds for all chunks; group 3 branches once (boundary only j0=4080).

#define L_DIM  8192
#define C4     64      // 256 f32 channels = 64 float4 lanes
#define J_OUT  4096
#define JPT    16      // outputs per thread along L
#define BY     2       // thread.y chunks per block

__device__ __forceinline__ float4 f4max(float4 a, float4 b) {
    return make_float4(fmaxf(a.x, b.x), fmaxf(a.y, b.y),
                       fmaxf(a.z, b.z), fmaxf(a.w, b.w));
}

__device__ __forceinline__ float4 f4blend(float4 a, float4 b, float4 c, float4 d,
                                          float w0, float w1, float w2, float w3) {
    float4 o;
    o.x = w0 * a.x + w1 * b.x + w2 * c.x + w3 * d.x;
    o.y = w0 * a.y + w1 * b.y + w2 * c.y + w3 * d.y;
    o.z = w0 * a.z + w1 * b.z + w2 * c.z + w3 * d.z;
    o.w = w0 * a.w + w1 * b.w + w2 * c.w + w3 * d.w;
    return o;
}

__global__ void __launch_bounds__(128)
mbp1d_kernel(const float4* __restrict__ x,
             const float*  __restrict__ blur,
             const float*  __restrict__ avg,
             float4* __restrict__ z)
{
    // Fold blur (b0,b1,b2) and avg (a0,a1) into 4 taps over m[]
    const float b0 = blur[0], b1 = blur[1], b2 = blur[2];
    const float a0 = avg[0],  a1 = avg[1];
    const float w0 = a0 * b0;
    const float w1 = a0 * b1 + a1 * b0;
    const float w2 = a0 * b2 + a1 * b1;
    const float w3 = a1 * b2;

    const int c  = threadIdx.x;                                   // 0..63 float4 lane
    const int b  = blockIdx.y;                                    // batch
    const int j0 = (blockIdx.x * BY + threadIdx.y) * JPT;         // first output row

    const float4* xb = x + (size_t)b * L_DIM * C4 + c;
    float4*       zb = z + ((size_t)b * J_OUT + j0) * C4 + c;

    const float4 zero = make_float4(0.f, 0.f, 0.f, 0.f);

    // Rolling state at group top for output j:
    //   mA = m[2j-1], mB = m[2j], xlast = x[2j+1]
    float4 mA, mB, xlast;
    {
        const float4 x0 = xb[(size_t)(2 * j0) * C4];
        const float4 x1 = xb[(size_t)(2 * j0 + 1) * C4];
        if (j0 == 0) {
            mA = zero;                                            // m[-1] = 0 (pad)
        } else {
            const float4 xm1 = xb[(size_t)(2 * j0 - 1) * C4];
            mA = f4max(xm1, x0);
        }
        mB = f4max(x0, x1);
        xlast = x1;
    }

    // Groups 0..2: rows needed run up to 2*j0 + 2 + 8*g + 7 <= 2*4080 + 31
    // = 8191 at most -> always in-bounds, no guards.
    #pragma unroll
    for (int g = 0; g < 3; ++g) {
        const int j = j0 + 4 * g;
        const float4* p = xb + (size_t)(2 * j + 2) * C4;

        // 8 independent loads issued before ANY consumer — forced batch.
        const float4 r0 = p[0 * C4];
        const float4 r1 = p[1 * C4];
        const float4 r2 = p[2 * C4];
        const float4 r3 = p[3 * C4];
        const float4 r4 = p[4 * C4];
        const float4 r5 = p[5 * C4];
        const float4 r6 = p[6 * C4];
        const float4 r7 = p[7 * C4];

        const float4 m1 = f4max(xlast, r0);   // m[2j+1]
        const float4 m2 = f4max(r0, r1);      // m[2j+2]
        const float4 m3 = f4max(r1, r2);
        const float4 m4 = f4max(r2, r3);
        const float4 m5 = f4max(r3, r4);
        const float4 m6 = f4max(r4, r5);
        const float4 m7 = f4max(r5, r6);
        const float4 m8 = f4max(r6, r7);

        zb[(size_t)(4 * g + 0) * C4] = f4blend(mA, mB, m1, m2, w0, w1, w2, w3);
        zb[(size_t)(4 * g + 1) * C4] = f4blend(m1, m2, m3, m4, w0, w1, w2, w3);
        zb[(size_t)(4 * g + 2) * C4] = f4blend(m3, m4, m5, m6, w0, w1, w2, w3);
        zb[(size_t)(4 * g + 3) * C4] = f4blend(m5, m6, m7, m8, w0, w1, w2, w3);

        mA = m7;
        mB = m8;
        xlast = r7;
    }

    // Group 3: only the very last chunk (j0 = 4080) runs off the end.
    if (j0 != J_OUT - JPT) {
        const int j = j0 + 12;
        const float4* p = xb + (size_t)(2 * j + 2) * C4;

        const float4 r0 = p[0 * C4];
        const float4 r1 = p[1 * C4];
        const float4 r2 = p[2 * C4];
        const float4 r3 = p[3 * C4];
        const float4 r4 = p[4 * C4];
        const float4 r5 = p[5 * C4];
        const float4 r6 = p[6 * C4];
        const float4 r7 = p[7 * C4];

        const float4 m1 = f4max(xlast, r0);
        const float4 m2 = f4max(r0, r1);
        const float4 m3 = f4max(r1, r2);
        const float4 m4 = f4max(r2, r3);
        const float4 m5 = f4max(r3, r4);
        const float4 m6 = f4max(r4, r5);
        const float4 m7 = f4max(r5, r6);
        const float4 m8 = f4max(r6, r7);

        zb[(size_t)12 * C4] = f4blend(mA, mB, m1, m2, w0, w1, w2, w3);
        zb[(size_t)13 * C4] = f4blend(m1, m2, m3, m4, w0, w1, w2, w3);
        zb[(size_t)14 * C4] = f4blend(m3, m4, m5, m6, w0, w1, w2, w3);
        zb[(size_t)15 * C4] = f4blend(m5, m6, m7, m8, w0, w1, w2, w3);
    } else {
        // j = 4092..4095. Rows 8186..8191 exist; x[8192..] do not.
        // m[8185]=max(xlast,r0) ... m[8190]=max(r4,r5), m[8191]=r5 (NEG_INF
        // pad makes it x[8191]), m[8192]=0 (zero pad).
        const float4* p = xb + (size_t)8186 * C4;

        const float4 r0 = p[0 * C4];
        const float4 r1 = p[1 * C4];
        const float4 r2 = p[2 * C4];
        const float4 r3 = p[3 * C4];
        const float4 r4 = p[4 * C4];
        const float4 r5 = p[5 * C4];

        const float4 m1 = f4max(xlast, r0);   // m[8185]
        const float4 m2 = f4max(r0, r1);      // m[8186]
        const float4 m3 = f4max(r1, r2);      // m[8187]
        const float4 m4 = f4max(r2, r3);      // m[8188]
        const float4 m5 = f4max(r3, r4);      // m[8189]
        const float4 m6 = f4max(r4, r5);      // m[8190]
        const float4 m7 = r5;                 // m[8191] = x[8191]
        const float4 m8 = zero;               // m[8192] = 0

        zb[(size_t)12 * C4] = f4blend(mA, mB, m1, m2, w0, w1, w2, w3);
        zb[(size_t)13 * C4] = f4blend(m1, m2, m3, m4, w0, w1, w2, w3);
        zb[(size_t)14 * C4] = f4blend(m3, m4, m5, m6, w0, w1, w2, w3);
        zb[(size_t)15 * C4] = f4blend(m5, m6, m7, m8, w0, w1, w2, w3);
    }
}

extern "C" void kernel_launch(void* const* d_in, const int* in_sizes, int n_in,
                              void* d_out, int out_size)
{
    const float4* x    = (const float4*)d_in[0];   // (16, 8192, 256) f32
    const float*  blur = (const float*)d_in[1];    // (3,1,1)
    const float*  avg  = (const float*)d_in[2];    // (2,1,1)
    float4*       z    = (float4*)d_out;           // (16, 4096, 256) f32

    (void)in_sizes; (void)n_in; (void)out_size;

    dim3 block(C4, BY);                            // (64, 2) = 128 threads
    dim3 grid(J_OUT / (BY * JPT), 16);             // (128, 16) = 2048 blocks
    mbp1d_kernel<<<grid, block>>>(x, blur, avg, z);
}